// round 15
// baseline (speedup 1.0000x reference)
#include <cuda_runtime.h>
#include <cuda_bf16.h>
#include <cuda_fp16.h>
#include <cstdint>
#include <math.h>

#define Bsz 64
#define TT  512
#define Din 256
#define Hh  512
#define G   2048   /* 4*H */

typedef unsigned long long ull;
typedef __nv_bfloat16 bf16;

// ---------------- scratch (static device globals; no allocation) ----------------
__device__ float g_gx0 [(size_t)2*TT*Bsz*G];    // [d][t][b][4H]
__device__ float g_gx1f[(size_t)TT*Bsz*G];      // [t][b][4H]
__device__ float g_gx1b[Bsz*G];
__device__ float g_h1f[Bsz*Hh];                 // layer1 fwd h (final used)
__device__ float g_hb[Bsz*Hh];                  // layer1 bwd one-step hidden
__device__ unsigned g_flags[6*64*8];            // per-CTA step flags, 32B padded
                                                // doms: scan0 (dir,bg) 0..3; scan1 bg 4..5

// bf16 split operands for projection GEMMs (projections stay 3-term bf16)
__device__ bf16 g_xhi[(size_t)TT*Bsz*Din],   g_xlo[(size_t)TT*Bsz*Din];
__device__ bf16 g_o0hi[(size_t)TT*Bsz*2*Hh], g_o0lo[(size_t)TT*Bsz*2*Hh];
__device__ bf16 g_w0hi[2*G*Din],  g_w0lo[2*G*Din];
__device__ bf16 g_w1hi[2*G*2*Hh], g_w1lo[2*G*2*Hh];

// h state in MMA A-fragment layout (fp16, M=32 per batch-group chain):
//   flat: [dir][bg][pingpong][ kt(32) x mt(2) x lane(32) x reg(4) = 8192 words ]
__device__ uint32_t g_f0[2][2][16384];          // 65536 words = 2 dir x 2 bg x 2 pp x 8192
__device__ uint32_t g_f1[2][16384];             // 32768 words = 2 bg x 2 pp x 8192
// W_hh in MMA B-fragment layout (fp16 hi/lo 2-term), 16384 words per CTA:
//   [kt32][nt4][lane32][b0h,b1h,b0l,b1l]
__device__ uint32_t g_wf0[2*64*16384];          // [dir][cta64]
__device__ uint32_t g_wf1[64*16384];            // [cta64]

__device__ __forceinline__ float sigf(float x) { return 1.0f / (1.0f + __expf(-x)); }
__device__ __forceinline__ float tanhfast(float x) {
    float e = __expf(-2.0f * fabsf(x));
    float r = (1.0f - e) / (1.0f + e);
    return copysignf(r, x);
}

// ---------------- mma.sync helpers ----------------
__device__ __forceinline__ uint32_t smem_u32(const void* p) {
    uint32_t a;
    asm("{ .reg .u64 t; cvta.to.shared.u64 t, %1; cvt.u32.u64 %0, t; }" : "=r"(a) : "l"(p));
    return a;
}
__device__ __forceinline__ void ldsm4(uint32_t* r, uint32_t addr) {
    asm volatile("ldmatrix.sync.aligned.m8n8.x4.shared.b16 {%0,%1,%2,%3}, [%4];"
                 : "=r"(r[0]), "=r"(r[1]), "=r"(r[2]), "=r"(r[3]) : "r"(addr));
}
__device__ __forceinline__ void mma16816(float* d, const uint32_t* a,
                                         uint32_t b0, uint32_t b1) {
    asm volatile(
        "mma.sync.aligned.m16n8k16.row.col.f32.bf16.bf16.f32 "
        "{%0,%1,%2,%3}, {%4,%5,%6,%7}, {%8,%9}, {%0,%1,%2,%3};"
        : "+f"(d[0]), "+f"(d[1]), "+f"(d[2]), "+f"(d[3])
        : "r"(a[0]), "r"(a[1]), "r"(a[2]), "r"(a[3]), "r"(b0), "r"(b1));
}
__device__ __forceinline__ void mma16816h(float* d, const uint32_t* a,
                                          uint32_t b0, uint32_t b1) {
    asm volatile(
        "mma.sync.aligned.m16n8k16.row.col.f32.f16.f16.f32 "
        "{%0,%1,%2,%3}, {%4,%5,%6,%7}, {%8,%9}, {%0,%1,%2,%3};"
        : "+f"(d[0]), "+f"(d[1]), "+f"(d[2]), "+f"(d[3])
        : "r"(a[0]), "r"(a[1]), "r"(a[2]), "r"(a[3]), "r"(b0), "r"(b1));
}

// ---------------- hi/lo pack helpers ----------------
__device__ __forceinline__ void wfrag_pack_h(float wx, float wy, uint32_t& whi, uint32_t& wlo) {
    __half h0 = __float2half_rn(wx), h1 = __float2half_rn(wy);
    __half l0 = __float2half_rn(wx - __half2float(h0));
    __half l1 = __float2half_rn(wy - __half2float(h1));
    whi = (uint32_t)__half_as_ushort(h0) | ((uint32_t)__half_as_ushort(h1) << 16);
    wlo = (uint32_t)__half_as_ushort(l0) | ((uint32_t)__half_as_ushort(l1) << 16);
}

// ---------------- prep0 = split_x + split w_ih0 + wfrag0 + state/flag init ------
__global__ void k_prep0(const float* __restrict__ x, const float* __restrict__ w_ih0,
                        const float* __restrict__ w_hh0) {
    const int blk = blockIdx.x, tid = threadIdx.x;
    if (blk < 32768) {                               // x[b][t][d] -> hi/lo [t][b][d]
        int i = blk * 256 + tid;
        int d = i & (Din - 1), t = (i >> 8) & (TT - 1), b = i >> 17;
        float v = x[i];
        bf16 h = __float2bfloat16(v);
        size_t o = ((size_t)t * Bsz + b) * Din + d;
        g_xhi[o] = h;
        g_xlo[o] = __float2bfloat16(v - __bfloat162float(h));
    } else if (blk < 36864) {                        // w_ih0 split
        int i = (blk - 32768) * 256 + tid;
        float v = w_ih0[i];
        bf16 h = __float2bfloat16(v);
        g_w0hi[i] = h;
        g_w0lo[i] = __float2bfloat16(v - __bfloat162float(h));
    } else if (blk < 40960) {                        // wfrag0 (fp16 hi/lo)
        int idx = (blk - 36864) * 256 + tid;         // < 1048576
        int d  = idx >> 19;
        int r  = (idx >> 8) & 2047;
        int k  = (idx & 255) * 2;
        int gg = r >> 9, jj = r & 511;
        int cta = jj >> 3, u = jj & 7;
        int ngl = gg * 8 + u, nt = ngl >> 3, nc = ngl & 7;
        int kt = k >> 4;
        int lane2 = (nc << 2) | ((k & 7) >> 1);
        int reg = ((k & 15) >= 8) ? 1 : 0;
        float2 wv = *(const float2*)(w_hh0 + ((size_t)d * G + r) * Hh + k);
        uint32_t whi, wlo; wfrag_pack_h(wv.x, wv.y, whi, wlo);
        size_t base = ((size_t)d * 64 + cta) * 16384 + ((size_t)(kt * 4 + nt) * 32 + lane2) * 4;
        g_wf0[base + reg]     = whi;
        g_wf0[base + reg + 2] = wlo;
    } else {                                         // state + flag init
        int i = (blk - 40960) * 256 + tid;           // < 131072
        if (i < 65536) (&g_f0[0][0][0])[i] = 0u;
        if (i < 32768) (&g_f1[0][0])[i]    = 0u;
        if (i < 6*64*8) g_flags[i] = 0u;
    }
}

// prep1 = split w_ih1 + wfrag1 (fp16 hi/lo, 64-CTA layout)
__global__ void k_prep1(const float* __restrict__ w_ih1, const float* __restrict__ w_hh1) {
    const int blk = blockIdx.x, tid = threadIdx.x;
    if (blk < 16384) {                               // w_ih1 split (4M elems)
        int i = blk * 256 + tid;
        float v = w_ih1[i];
        bf16 h = __float2bfloat16(v);
        g_w1hi[i] = h;
        g_w1lo[i] = __float2bfloat16(v - __bfloat162float(h));
    } else {                                         // wfrag1
        int idx = (blk - 16384) * 256 + tid;         // < 524288
        int r  = idx >> 8;
        int k  = (idx & 255) * 2;
        int gg = r >> 9, jj = r & 511;
        int cta = jj >> 3, u = jj & 7;
        int ngl = gg * 8 + u, nt = ngl >> 3, nc = ngl & 7;
        int kt = k >> 4;
        int lane2 = (nc << 2) | ((k & 7) >> 1);
        int reg = ((k & 15) >= 8) ? 1 : 0;
        float2 wv = *(const float2*)(w_hh1 + (size_t)r * Hh + k);
        uint32_t whi, wlo; wfrag_pack_h(wv.x, wv.y, whi, wlo);
        size_t base = (size_t)cta * 16384 + ((size_t)(kt * 4 + nt) * 32 + lane2) * 4;
        g_wf1[base + reg]     = whi;
        g_wf1[base + reg + 2] = wlo;
    }
}

// ---------------- HMMA bf16-split projection GEMM (z-dim selects weight slice) --
#define MMSM (2 * 4 * 128 * 40 * 2 + 512)

__device__ __forceinline__ uint4 g_ld4(const bf16* __restrict__ src, int K,
                                       int row, int k0, int q, int rowsv) {
    if (row < rowsv)
        return *reinterpret_cast<const uint4*>(src + (size_t)row * K + k0 + q * 8);
    return make_uint4(0u, 0u, 0u, 0u);
}

__global__ void __launch_bounds__(256) k_mma_gemm(
    const bf16* __restrict__ Ahi, const bf16* __restrict__ Alo,
    const bf16* __restrict__ Bhi, const bf16* __restrict__ Blo,
    const float* __restrict__ bia, const float* __restrict__ bib,
    float* __restrict__ C, int M, int K,
    size_t bzs, size_t czs, int biazs)
{
    const int z = blockIdx.z;
    Bhi += (size_t)z * bzs; Blo += (size_t)z * bzs;
    C   += (size_t)z * czs;
    bia += (size_t)z * biazs; bib += (size_t)z * biazs;

    extern __shared__ __align__(16) char smx[];
    bf16*  sbase = (bf16*)smx;
    float* bsum  = (float*)(smx + 81920);
    const int tid = threadIdx.x, wid = tid >> 5, lane = tid & 31;
    const int bn = blockIdx.x << 7, bm = blockIdx.y << 7;
    const int wm = wid >> 2, wn = wid & 3;
    const int av = (M - bm < 128) ? (M - bm) : 128;

    if (tid < 128) bsum[tid] = bia[bn + tid] + bib[bn + tid];

    const bf16* gAh = Ahi + (size_t)bm * K;
    const bf16* gAl = Alo + (size_t)bm * K;
    const bf16* gBh = Bhi + (size_t)bn * K;
    const bf16* gBl = Blo + (size_t)bn * K;

    const int r0 = tid >> 2, qq = tid & 3;

    {
        uint4 v[4][2];
        v[0][0] = g_ld4(gAh, K, r0, 0, qq, av);  v[0][1] = g_ld4(gAh, K, r0+64, 0, qq, av);
        v[1][0] = g_ld4(gAl, K, r0, 0, qq, av);  v[1][1] = g_ld4(gAl, K, r0+64, 0, qq, av);
        v[2][0] = g_ld4(gBh, K, r0, 0, qq, 128); v[2][1] = g_ld4(gBh, K, r0+64, 0, qq, 128);
        v[3][0] = g_ld4(gBl, K, r0, 0, qq, 128); v[3][1] = g_ld4(gBl, K, r0+64, 0, qq, 128);
#pragma unroll
        for (int t2 = 0; t2 < 4; t2++) {
            bf16* d = sbase + t2 * 5120;
            *reinterpret_cast<uint4*>(d + r0 * 40 + qq * 8)        = v[t2][0];
            *reinterpret_cast<uint4*>(d + (r0 + 64) * 40 + qq * 8) = v[t2][1];
        }
    }
    __syncthreads();

    float acc[4][4][4];
#pragma unroll
    for (int mi = 0; mi < 4; mi++)
#pragma unroll
        for (int ni = 0; ni < 4; ni++)
#pragma unroll
            for (int r = 0; r < 4; r++) acc[mi][ni][r] = 0.0f;

    const uint32_t sbu  = smem_u32(sbase);
    const uint32_t arow = 2u * (((uint32_t)(lane & 15)) * 40u + ((uint32_t)(lane >> 4)) * 8u);
    const int NKB = K >> 5;

    for (int kb = 0; kb < NKB; kb++) {
        uint4 v[4][2];
        const bool pf = (kb + 1 < NKB);
        if (pf) {
            const int k0 = (kb + 1) << 5;
            v[0][0] = g_ld4(gAh, K, r0, k0, qq, av);  v[0][1] = g_ld4(gAh, K, r0+64, k0, qq, av);
            v[1][0] = g_ld4(gAl, K, r0, k0, qq, av);  v[1][1] = g_ld4(gAl, K, r0+64, k0, qq, av);
            v[2][0] = g_ld4(gBh, K, r0, k0, qq, 128); v[2][1] = g_ld4(gBh, K, r0+64, k0, qq, 128);
            v[3][0] = g_ld4(gBl, K, r0, k0, qq, 128); v[3][1] = g_ld4(gBl, K, r0+64, k0, qq, 128);
        }

        const uint32_t base = sbu + ((kb & 1) ? 40960u : 0u);
        const uint32_t aA = base + arow + (uint32_t)wm * 5120u;
        const uint32_t aB = base + 20480u + arow + (uint32_t)wn * 2560u;
#pragma unroll
        for (int kh = 0; kh < 2; kh++) {
            const uint32_t ko = (uint32_t)kh * 32u;
            uint32_t ah[4][4], al_[4][4], bh[2][4], bl_[2][4];
#pragma unroll
            for (int mi = 0; mi < 4; mi++) {
                ldsm4(ah[mi],  aA + (uint32_t)mi * 1280u + ko);
                ldsm4(al_[mi], aA + 10240u + (uint32_t)mi * 1280u + ko);
            }
#pragma unroll
            for (int nj = 0; nj < 2; nj++) {
                ldsm4(bh[nj],  aB + (uint32_t)nj * 1280u + ko);
                ldsm4(bl_[nj], aB + 10240u + (uint32_t)nj * 1280u + ko);
            }
#pragma unroll
            for (int mi = 0; mi < 4; mi++) {
#pragma unroll
                for (int ni = 0; ni < 4; ni++) {
                    const int nj = ni >> 1, sb_ = ni & 1;
                    mma16816(acc[mi][ni], ah[mi],  bh[nj][sb_], bh[nj][sb_ + 2]);
                    mma16816(acc[mi][ni], ah[mi],  bl_[nj][sb_], bl_[nj][sb_ + 2]);
                    mma16816(acc[mi][ni], al_[mi], bh[nj][sb_], bh[nj][sb_ + 2]);
                }
            }
        }

        if (pf) {
            bf16* d0 = sbase + ((kb + 1) & 1) * 20480;
#pragma unroll
            for (int t2 = 0; t2 < 4; t2++) {
                bf16* d = d0 + t2 * 5120;
                *reinterpret_cast<uint4*>(d + r0 * 40 + qq * 8)        = v[t2][0];
                *reinterpret_cast<uint4*>(d + (r0 + 64) * 40 + qq * 8) = v[t2][1];
            }
        }
        __syncthreads();
    }

#pragma unroll
    for (int mi = 0; mi < 4; mi++) {
#pragma unroll
        for (int ni = 0; ni < 4; ni++) {
            const int coll = wn * 32 + ni * 8 + (lane & 3) * 2;
            const int rowa = bm + wm * 64 + mi * 16 + (lane >> 2);
            const float bx = bsum[coll], by = bsum[coll + 1];
            if (rowa < M) {
                float2 p = make_float2(acc[mi][ni][0] + bx, acc[mi][ni][1] + by);
                *reinterpret_cast<float2*>(C + (size_t)rowa * G + bn + coll) = p;
            }
            if (rowa + 8 < M) {
                float2 p = make_float2(acc[mi][ni][2] + bx, acc[mi][ni][3] + by);
                *reinterpret_cast<float2*>(C + (size_t)(rowa + 8) * G + bn + coll) = p;
            }
        }
    }
}

// ---------------- persistent tensor-core LSTM scan, 2 interleaved batch chains --
// Batches are independent recurrences: split into 2 groups of 32, interleaved on
// the same CTA so one chain's L2 sync round-trip hides behind the other's compute.
// Per sub-step (chain): M=32, warp (kh,mh) = (k-quarter, m-tile), all 8 A frags
// preloaded (8 ldcg.v4 in flight). fp16 h x fp16 hi/lo w_hh, fp32 accum.
template<bool L0>
__global__ void __launch_bounds__(256, 1) k_scan_mma() {
    constexpr int NU = 8, NP = 34;
    __shared__ float gd[4][32][NP];
    __shared__ float c_sm[2][32][NU];

    const int tid = threadIdx.x, wid = tid >> 5, lane = tid & 31;
    const int kh = wid >> 1, mh = wid & 1;
    const int tig = lane & 3, gid = lane >> 2;

    const int cta = blockIdx.x;                  // 0..63 unit-slice
    const int dir = L0 ? blockIdx.y : 0;
    const int rev = L0 ? dir : 0;
    const int jbase = cta * NU;

    const float* gx = L0 ? (g_gx0 + (size_t)dir * TT * Bsz * G) : g_gx1f;
    const uint4* wf4 = L0 ? ((const uint4*)g_wf0) + ((size_t)dir * 64 + cta) * 4096
                          : ((const uint4*)g_wf1) + (size_t)cta * 4096;
    uint32_t* fbase = L0 ? (&g_f0[0][0][0] + (size_t)dir * 32768) : &g_f1[0][0];

    for (int i = tid; i < 2 * 32 * NU; i += 256) (&c_sm[0][0][0])[i] = 0.f;

    // pointwise role (tid<128): batch-local pbl 0..31, unit pair ppi 0..3
    const int pbl = (tid >> 2) & 31;
    const int ppi = tid & 3;
    const int jg  = jbase + 2 * ppi;
    const int fc = jg & 15, fr = pbl & 15, fmt = (pbl >> 4) & 1, fkt = jg >> 4;
    const int flane = ((fr & 7) << 2) | ((fc & 7) >> 1);
    const int freg  = ((fr >> 3) & 1) | (((fc >> 3) & 1) << 1);
    const int faddr = ((fkt * 2 + fmt) * 32 + flane) * 4 + freg;
    const bool pw = (tid < 128);

    __syncthreads();

    for (int t = 0; t < TT; t++) {
        const int tt = rev ? (TT - 1 - t) : t;
#pragma unroll
        for (int bg = 0; bg < 2; bg++) {
            uint32_t* fch = fbase + bg * 16384;
            const uint32_t* fin = fch + ((t & 1) ? 8192 : 0);
            uint32_t*      fout = fch + ((t & 1) ? 0 : 8192);
            unsigned* dom = g_flags + (size_t)(L0 ? (dir * 2 + bg) : (4 + bg)) * 512;
            unsigned* flag_me = dom + cta * 8;
            const unsigned* flag_src = dom + (16 * kh + (lane & 15)) * 8;
            const int b = bg * 32 + pbl;

            // gate pre-activations (independent of h; issued before the wait)
            float2 pre[4];
            if (pw) {
                const float* gp = gx + ((size_t)tt * Bsz + b) * G + jg;
                pre[0] = __ldcs((const float2*)gp);
                pre[1] = __ldcs((const float2*)(gp + 512));
                pre[2] = __ldcs((const float2*)(gp + 1024));
                pre[3] = __ldcs((const float2*)(gp + 1536));
            }

            // wait for this chain's producers (should already be satisfied:
            // the other chain's compute covered the propagation latency)
            if (t > 0) {
                unsigned v;
                do {
                    asm volatile("ld.acquire.gpu.global.u32 %0, [%1];"
                                 : "=r"(v) : "l"(flag_src) : "memory");
                } while (v < (unsigned)t);
                __syncwarp();
            }

            // preload all 8 A fragments (8 ldcg.v4 in flight)
            uint4 Ar[8];
#pragma unroll
            for (int k8 = 0; k8 < 8; k8++)
                Ar[k8] = __ldcg((const uint4*)
                    (fin + ((size_t)((kh * 8 + k8) * 2 + mh) * 32 + lane) * 4));

            float acc[4][4];
#pragma unroll
            for (int nt = 0; nt < 4; nt++)
#pragma unroll
                for (int r = 0; r < 4; r++) acc[nt][r] = 0.f;

#pragma unroll
            for (int k8 = 0; k8 < 8; k8++) {
                const int kt = kh * 8 + k8;
                uint32_t a[4] = {Ar[k8].x, Ar[k8].y, Ar[k8].z, Ar[k8].w};
#pragma unroll
                for (int nt = 0; nt < 4; nt++) {
                    uint4 Bv = __ldg(wf4 + (size_t)(kt * 4 + nt) * 32 + lane);
                    mma16816h(acc[nt], a, Bv.x, Bv.y);   // h * w_hi
                    mma16816h(acc[nt], a, Bv.z, Bv.w);   // h * w_lo
                }
            }

            // dump K-quarter partials to smem
            const int rb = mh * 16 + gid;
#pragma unroll
            for (int nt = 0; nt < 4; nt++) {
                const int col = nt * 8 + tig * 2;
                *(float2*)&gd[kh][rb][col]     = make_float2(acc[nt][0], acc[nt][1]);
                *(float2*)&gd[kh][rb + 8][col] = make_float2(acc[nt][2], acc[nt][3]);
            }
            __syncthreads();

            // pointwise + h publish (fp16 pair: one word)
            float hv0 = 0.f, hv1 = 0.f;
            if (pw) {
#pragma unroll
                for (int uu = 0; uu < 2; uu++) {
                    const int u = 2 * ppi + uu;
                    float gi = uu ? pre[0].y : pre[0].x;
                    float gf = uu ? pre[1].y : pre[1].x;
                    float gc = uu ? pre[2].y : pre[2].x;
                    float go = uu ? pre[3].y : pre[3].x;
#pragma unroll
                    for (int q = 0; q < 4; q++) {
                        gi += gd[q][pbl][0 * NU + u];
                        gf += gd[q][pbl][1 * NU + u];
                        gc += gd[q][pbl][2 * NU + u];
                        go += gd[q][pbl][3 * NU + u];
                    }
                    float cc = sigf(gf) * c_sm[bg][pbl][u] + sigf(gi) * tanhfast(gc);
                    float hh = sigf(go) * tanhfast(cc);
                    c_sm[bg][pbl][u] = cc;
                    if (uu == 0) hv0 = hh; else hv1 = hh;
                }
                __half2 hp = __floats2half2_rn(hv0, hv1);
                __stcg((unsigned int*)&fout[faddr], *reinterpret_cast<uint32_t*>(&hp));
            }
            __syncthreads();
            if (tid == 0) {
                asm volatile("st.release.gpu.global.u32 [%0], %1;"
                             :: "l"(flag_me), "r"((unsigned)(t + 1)) : "memory");
            }

            // side outputs off the critical path (bf16 hi/lo of exact fp32 h)
            if (pw) {
                if (L0) {
                    bf16 h0h = __float2bfloat16(hv0);
                    bf16 h1h = __float2bfloat16(hv1);
                    bf16 h0l = __float2bfloat16(hv0 - __bfloat162float(h0h));
                    bf16 h1l = __float2bfloat16(hv1 - __bfloat162float(h1h));
                    uint32_t whi = (uint32_t)__bfloat16_as_ushort(h0h) |
                                   ((uint32_t)__bfloat16_as_ushort(h1h) << 16);
                    uint32_t wlo = (uint32_t)__bfloat16_as_ushort(h0l) |
                                   ((uint32_t)__bfloat16_as_ushort(h1l) << 16);
                    const size_t oo = ((size_t)tt * Bsz + b) * (2 * Hh) + (size_t)dir * Hh + jg;
                    __stcg((unsigned int*)&g_o0hi[oo], whi);
                    __stcg((unsigned int*)&g_o0lo[oo], wlo);
                } else {
                    g_h1f[(size_t)b * Hh + jg]     = hv0;
                    g_h1f[(size_t)b * Hh + jg + 1] = hv1;
                }
            }
        }
    }
}

// layer1 backward at t=T-1: first step of reverse scan from zero state
__global__ void k_l1bwd() {
    int i = blockIdx.x * 256 + threadIdx.x;
    int b = i >> 9, j = i & 511;
    const float* gxp = g_gx1b + b * G;
    float gi = gxp[j], gc = gxp[2 * Hh + j], go = gxp[3 * Hh + j];
    float c = sigf(gi) * tanhfast(gc);
    float h = sigf(go) * tanhfast(c);
    g_hb[b * Hh + j] = h;
}

// ---------------- layernorm + MLP head ----------------
__global__ void __launch_bounds__(256) k_head(
    const float* __restrict__ ln_g, const float* __restrict__ ln_b,
    const float* __restrict__ w1,   const float* __restrict__ b1,
    const float* __restrict__ w2,   const float* __restrict__ b2,
    float* __restrict__ out)
{
    int b = blockIdx.x, tid = threadIdx.x;
    __shared__ float v[1024];
    __shared__ float red[256];
    for (int i = tid; i < Hh; i += 256) {
        v[i]      = g_h1f[b * Hh + i];
        v[Hh + i] = g_hb[b * Hh + i];
    }
    __syncthreads();
    float s = 0.f;
    for (int i = tid; i < 1024; i += 256) s += v[i];
    red[tid] = s; __syncthreads();
    for (int st = 128; st > 0; st >>= 1) { if (tid < st) red[tid] += red[tid + st]; __syncthreads(); }
    float mu = red[0] * (1.0f / 1024.0f);
    __syncthreads();
    s = 0.f;
    for (int i = tid; i < 1024; i += 256) { float dd = v[i] - mu; s += dd * dd; }
    red[tid] = s; __syncthreads();
    for (int st = 128; st > 0; st >>= 1) { if (tid < st) red[tid] += red[tid + st]; __syncthreads(); }
    float rstd = rsqrtf(red[0] * (1.0f / 1024.0f) + 1e-5f);
    __syncthreads();
    for (int i = tid; i < 1024; i += 256) v[i] = (v[i] - mu) * rstd * ln_g[i] + ln_b[i];
    __syncthreads();
    float part = 0.f;
    for (int jj = tid; jj < Hh; jj += 256) {
        float acc = b1[jj];
        const float* wr = w1 + (size_t)jj * 1024;
#pragma unroll 4
        for (int k2 = 0; k2 < 1024; k2++) acc += v[k2] * wr[k2];
        part += fmaxf(acc, 0.f) * w2[jj];
    }
    red[tid] = part; __syncthreads();
    for (int st = 128; st > 0; st >>= 1) { if (tid < st) red[tid] += red[tid + st]; __syncthreads(); }
    if (tid == 0) out[b] = red[0] + b2[0];
}

// ---------------- launch ----------------
extern "C" void kernel_launch(void* const* d_in, const int* in_sizes, int n_in,
                              void* d_out, int out_size)
{
    (void)in_sizes; (void)n_in; (void)out_size;
    const float* x     = (const float*)d_in[0];
    const float* w_ih0 = (const float*)d_in[1];
    const float* w_hh0 = (const float*)d_in[2];
    const float* b_ih0 = (const float*)d_in[3];
    const float* b_hh0 = (const float*)d_in[4];
    const float* w_ih1 = (const float*)d_in[5];
    const float* w_hh1 = (const float*)d_in[6];
    const float* b_ih1 = (const float*)d_in[7];
    const float* b_hh1 = (const float*)d_in[8];
    const float* ln_g  = (const float*)d_in[9];
    const float* ln_b  = (const float*)d_in[10];
    const float* w1    = (const float*)d_in[11];
    const float* b1    = (const float*)d_in[12];
    const float* w2    = (const float*)d_in[13];
    const float* b2    = (const float*)d_in[14];
    float* out = (float*)d_out;

    cudaFuncSetAttribute(k_mma_gemm, cudaFuncAttributeMaxDynamicSharedMemorySize, MMSM);

    void *p_gx0, *p_gx1f, *p_gx1b;
    void *p_xhi, *p_xlo, *p_o0hi, *p_o0lo, *p_w0hi, *p_w0lo, *p_w1hi, *p_w1lo;
    cudaGetSymbolAddress(&p_gx0, g_gx0);
    cudaGetSymbolAddress(&p_gx1f, g_gx1f);
    cudaGetSymbolAddress(&p_gx1b, g_gx1b);
    cudaGetSymbolAddress(&p_xhi, g_xhi);   cudaGetSymbolAddress(&p_xlo, g_xlo);
    cudaGetSymbolAddress(&p_o0hi, g_o0hi); cudaGetSymbolAddress(&p_o0lo, g_o0lo);
    cudaGetSymbolAddress(&p_w0hi, g_w0hi); cudaGetSymbolAddress(&p_w0lo, g_w0lo);
    cudaGetSymbolAddress(&p_w1hi, g_w1hi); cudaGetSymbolAddress(&p_w1lo, g_w1lo);

    // our launch #3 (0-based) is what ncu -s 5 profiles (2 harness kernels first)
    k_prep0<<<41472, 256>>>(x, w_ih0, w_hh0);                            // 0

    // layer 0 input projections, both directions via gridDim.z=2
    k_mma_gemm<<<dim3(16, 256, 2), 256, MMSM>>>(                         // 1
        (bf16*)p_xhi, (bf16*)p_xlo, (bf16*)p_w0hi, (bf16*)p_w0lo,
        b_ih0, b_hh0, (float*)p_gx0, Bsz * TT, Din,
        (size_t)G * Din, (size_t)TT * Bsz * G, G);

    k_prep1<<<18432, 256>>>(w_ih1, w_hh1);                               // 2

    // layer 0 bidirectional scan  <- profiled
    k_scan_mma<true><<<dim3(64, 2), 256>>>();                            // 3

    // layer 1 fwd projection + bwd projection (only t = T-1)
    k_mma_gemm<<<dim3(16, 256, 1), 256, MMSM>>>(                         // 4
        (bf16*)p_o0hi, (bf16*)p_o0lo, (bf16*)p_w1hi, (bf16*)p_w1lo,
        b_ih1, b_hh1, (float*)p_gx1f, Bsz * TT, 2 * Hh, 0, 0, 0);
    k_mma_gemm<<<dim3(16, 1, 1), 256, MMSM>>>(                           // 5
        (bf16*)p_o0hi + (size_t)(TT - 1) * Bsz * 2 * Hh,
        (bf16*)p_o0lo + (size_t)(TT - 1) * Bsz * 2 * Hh,
        (bf16*)p_w1hi + (size_t)G * 2 * Hh, (bf16*)p_w1lo + (size_t)G * 2 * Hh,
        b_ih1 + G, b_hh1 + G, (float*)p_gx1b, Bsz, 2 * Hh, 0, 0, 0);

    // layer 1 forward scan (64 CTAs, 2 interleaved batch chains)
    k_scan_mma<false><<<64, 256>>>();                                    // 6

    k_l1bwd<<<128, 256>>>();                                             // 7
    k_head<<<64, 256>>>(ln_g, ln_b, w1, b1, w2, b2, out);                // 8
}

// round 16
// speedup vs baseline: 1.2694x; 1.2694x over previous
#include <cuda_runtime.h>
#include <cuda_bf16.h>
#include <cuda_fp16.h>
#include <cstdint>
#include <math.h>

#define Bsz 64
#define TT  512
#define Din 256
#define Hh  512
#define G   2048   /* 4*H */

typedef unsigned long long ull;
typedef __nv_bfloat16 bf16;

// ---------------- scratch (static device globals; no allocation) ----------------
__device__ float g_gx0 [(size_t)2*TT*Bsz*G];    // [d][t][b][4H]
__device__ float g_gx1f[(size_t)TT*Bsz*G];      // [t][b][4H]
__device__ float g_gx1b[Bsz*G];
__device__ float g_h1f[Bsz*Hh];                 // layer1 fwd h (final used)
__device__ float g_hb[Bsz*Hh];                  // layer1 bwd one-step hidden
__device__ unsigned g_flags[3*64*8];            // per-CTA step flags, 32B padded

// fp16 operands for projection GEMMs (A single fp16, B hi/lo fp16)
__device__ __half g_xh [(size_t)TT*Bsz*Din];    // x in [t][b][d]
__device__ __half g_o0h[(size_t)TT*Bsz*2*Hh];   // layer0 output [t][b][2H]
__device__ __half g_w0h[2*G*Din],  g_w0l[2*G*Din];
__device__ __half g_w1h[2*G*2*Hh], g_w1l[2*G*2*Hh];

// h state in MMA A-fragment layout (fp16, single term):
//   [kt(32)][mt(4)][lane(32)][reg0-3]  (4 words per lane-slot)
__device__ uint32_t g_f0[2][2][16384];          // [dir][pingpong]
__device__ uint32_t g_f1[2][16384];             // layer1 fwd [pingpong]
// W_hh in MMA B-fragment layout (fp16 hi/lo 2-term), 16384 words per CTA:
//   [kt32][nt4][lane32][b0h,b1h,b0l,b1l]
__device__ uint32_t g_wf0[2*64*16384];          // [dir][cta64]
__device__ uint32_t g_wf1[64*16384];            // [cta64]

__device__ __forceinline__ float sigf(float x) { return 1.0f / (1.0f + __expf(-x)); }
__device__ __forceinline__ float tanhfast(float x) {
    float e = __expf(-2.0f * fabsf(x));
    float r = (1.0f - e) / (1.0f + e);
    return copysignf(r, x);
}

// ---------------- mma.sync helpers ----------------
__device__ __forceinline__ uint32_t smem_u32(const void* p) {
    uint32_t a;
    asm("{ .reg .u64 t; cvta.to.shared.u64 t, %1; cvt.u32.u64 %0, t; }" : "=r"(a) : "l"(p));
    return a;
}
__device__ __forceinline__ void ldsm4(uint32_t* r, uint32_t addr) {
    asm volatile("ldmatrix.sync.aligned.m8n8.x4.shared.b16 {%0,%1,%2,%3}, [%4];"
                 : "=r"(r[0]), "=r"(r[1]), "=r"(r[2]), "=r"(r[3]) : "r"(addr));
}
__device__ __forceinline__ void mma16816h(float* d, const uint32_t* a,
                                          uint32_t b0, uint32_t b1) {
    asm volatile(
        "mma.sync.aligned.m16n8k16.row.col.f32.f16.f16.f32 "
        "{%0,%1,%2,%3}, {%4,%5,%6,%7}, {%8,%9}, {%0,%1,%2,%3};"
        : "+f"(d[0]), "+f"(d[1]), "+f"(d[2]), "+f"(d[3])
        : "r"(a[0]), "r"(a[1]), "r"(a[2]), "r"(a[3]), "r"(b0), "r"(b1));
}

// ---------------- hi/lo pack helpers ----------------
__device__ __forceinline__ void wfrag_pack_h(float wx, float wy, uint32_t& whi, uint32_t& wlo) {
    __half h0 = __float2half_rn(wx), h1 = __float2half_rn(wy);
    __half l0 = __float2half_rn(wx - __half2float(h0));
    __half l1 = __float2half_rn(wy - __half2float(h1));
    whi = (uint32_t)__half_as_ushort(h0) | ((uint32_t)__half_as_ushort(h1) << 16);
    wlo = (uint32_t)__half_as_ushort(l0) | ((uint32_t)__half_as_ushort(l1) << 16);
}

// ---------------- prep0 = x->fp16 + w_ih0 hi/lo + wfrag0 + state/flag init ------
__global__ void k_prep0(const float* __restrict__ x, const float* __restrict__ w_ih0,
                        const float* __restrict__ w_hh0) {
    const int blk = blockIdx.x, tid = threadIdx.x;
    if (blk < 32768) {                               // x[b][t][d] -> fp16 [t][b][d]
        int i = blk * 256 + tid;
        int d = i & (Din - 1), t = (i >> 8) & (TT - 1), b = i >> 17;
        g_xh[((size_t)t * Bsz + b) * Din + d] = __float2half_rn(x[i]);
    } else if (blk < 36864) {                        // w_ih0 hi/lo split
        int i = (blk - 32768) * 256 + tid;
        float v = w_ih0[i];
        __half h = __float2half_rn(v);
        g_w0h[i] = h;
        g_w0l[i] = __float2half_rn(v - __half2float(h));
    } else if (blk < 40960) {                        // wfrag0 (fp16 hi/lo)
        int idx = (blk - 36864) * 256 + tid;         // < 1048576
        int d  = idx >> 19;
        int r  = (idx >> 8) & 2047;
        int k  = (idx & 255) * 2;
        int gg = r >> 9, jj = r & 511;
        int cta = jj >> 3, u = jj & 7;
        int ngl = gg * 8 + u, nt = ngl >> 3, nc = ngl & 7;
        int kt = k >> 4;
        int lane2 = (nc << 2) | ((k & 7) >> 1);
        int reg = ((k & 15) >= 8) ? 1 : 0;
        float2 wv = *(const float2*)(w_hh0 + ((size_t)d * G + r) * Hh + k);
        uint32_t whi, wlo; wfrag_pack_h(wv.x, wv.y, whi, wlo);
        size_t base = ((size_t)d * 64 + cta) * 16384 + ((size_t)(kt * 4 + nt) * 32 + lane2) * 4;
        g_wf0[base + reg]     = whi;
        g_wf0[base + reg + 2] = wlo;
    } else {                                         // state + flag init
        int i = (blk - 40960) * 256 + tid;           // < 131072
        if (i < 65536) (&g_f0[0][0][0])[i] = 0u;
        if (i < 32768) (&g_f1[0][0])[i]    = 0u;
        if (i < 3*64*8) g_flags[i] = 0u;
    }
}

// prep1 = w_ih1 hi/lo split + wfrag1 (fp16 hi/lo, 64-CTA layout)
__global__ void k_prep1(const float* __restrict__ w_ih1, const float* __restrict__ w_hh1) {
    const int blk = blockIdx.x, tid = threadIdx.x;
    if (blk < 16384) {                               // w_ih1 split (4M elems)
        int i = blk * 256 + tid;
        float v = w_ih1[i];
        __half h = __float2half_rn(v);
        g_w1h[i] = h;
        g_w1l[i] = __float2half_rn(v - __half2float(h));
    } else {                                         // wfrag1
        int idx = (blk - 16384) * 256 + tid;         // < 524288
        int r  = idx >> 8;
        int k  = (idx & 255) * 2;
        int gg = r >> 9, jj = r & 511;
        int cta = jj >> 3, u = jj & 7;
        int ngl = gg * 8 + u, nt = ngl >> 3, nc = ngl & 7;
        int kt = k >> 4;
        int lane2 = (nc << 2) | ((k & 7) >> 1);
        int reg = ((k & 15) >= 8) ? 1 : 0;
        float2 wv = *(const float2*)(w_hh1 + (size_t)r * Hh + k);
        uint32_t whi, wlo; wfrag_pack_h(wv.x, wv.y, whi, wlo);
        size_t base = (size_t)cta * 16384 + ((size_t)(kt * 4 + nt) * 32 + lane2) * 4;
        g_wf1[base + reg]     = whi;
        g_wf1[base + reg + 2] = wlo;
    }
}

// ---------------- HMMA fp16 projection GEMM: A fp16, B = hi+lo fp16 (2 MMAs) ----
// C[M,2048] = A[M,K] @ (Bh+Bl)[2048,K]^T + bia + bib. 128x128x32 tile, 8 warps.
// smem: 2 stages x 3 tiles x [128][40] fp16 (stride 40 => conflict-free ldmatrix).
#define MMSM (2 * 3 * 128 * 40 * 2 + 512)

__device__ __forceinline__ uint4 g_ld4h(const __half* __restrict__ src, int K,
                                        int row, int k0, int q, int rowsv) {
    if (row < rowsv)
        return *reinterpret_cast<const uint4*>(src + (size_t)row * K + k0 + q * 8);
    return make_uint4(0u, 0u, 0u, 0u);
}

__global__ void __launch_bounds__(256) k_mma_gemm(
    const __half* __restrict__ A,
    const __half* __restrict__ Bh, const __half* __restrict__ Bl,
    const float* __restrict__ bia, const float* __restrict__ bib,
    float* __restrict__ C, int M, int K,
    size_t bzs, size_t czs, int biazs)
{
    const int z = blockIdx.z;
    Bh += (size_t)z * bzs; Bl += (size_t)z * bzs;
    C  += (size_t)z * czs;
    bia += (size_t)z * biazs; bib += (size_t)z * biazs;

    extern __shared__ __align__(16) char smx[];
    __half* sbase = (__half*)smx;                 // 2 stages x 3 tiles x 5120 halves
    float*  bsum  = (float*)(smx + 61440);
    const int tid = threadIdx.x, wid = tid >> 5, lane = tid & 31;
    const int bn = blockIdx.x << 7, bm = blockIdx.y << 7;
    const int wm = wid >> 2, wn = wid & 3;
    const int av = (M - bm < 128) ? (M - bm) : 128;

    if (tid < 128) bsum[tid] = bia[bn + tid] + bib[bn + tid];

    const __half* gA  = A  + (size_t)bm * K;
    const __half* gBh = Bh + (size_t)bn * K;
    const __half* gBl = Bl + (size_t)bn * K;

    const int r0 = tid >> 2, qq = tid & 3;

    {
        uint4 v[3][2];
        v[0][0] = g_ld4h(gA,  K, r0, 0, qq, av);  v[0][1] = g_ld4h(gA,  K, r0+64, 0, qq, av);
        v[1][0] = g_ld4h(gBh, K, r0, 0, qq, 128); v[1][1] = g_ld4h(gBh, K, r0+64, 0, qq, 128);
        v[2][0] = g_ld4h(gBl, K, r0, 0, qq, 128); v[2][1] = g_ld4h(gBl, K, r0+64, 0, qq, 128);
#pragma unroll
        for (int t2 = 0; t2 < 3; t2++) {
            __half* d = sbase + t2 * 5120;
            *reinterpret_cast<uint4*>(d + r0 * 40 + qq * 8)        = v[t2][0];
            *reinterpret_cast<uint4*>(d + (r0 + 64) * 40 + qq * 8) = v[t2][1];
        }
    }
    __syncthreads();

    float acc[4][4][4];
#pragma unroll
    for (int mi = 0; mi < 4; mi++)
#pragma unroll
        for (int ni = 0; ni < 4; ni++)
#pragma unroll
            for (int r = 0; r < 4; r++) acc[mi][ni][r] = 0.0f;

    const uint32_t sbu  = smem_u32(sbase);
    const uint32_t arow = 2u * (((uint32_t)(lane & 15)) * 40u + ((uint32_t)(lane >> 4)) * 8u);
    const int NKB = K >> 5;

    for (int kb = 0; kb < NKB; kb++) {
        uint4 v[3][2];
        const bool pf = (kb + 1 < NKB);
        if (pf) {
            const int k0 = (kb + 1) << 5;
            v[0][0] = g_ld4h(gA,  K, r0, k0, qq, av);  v[0][1] = g_ld4h(gA,  K, r0+64, k0, qq, av);
            v[1][0] = g_ld4h(gBh, K, r0, k0, qq, 128); v[1][1] = g_ld4h(gBh, K, r0+64, k0, qq, 128);
            v[2][0] = g_ld4h(gBl, K, r0, k0, qq, 128); v[2][1] = g_ld4h(gBl, K, r0+64, k0, qq, 128);
        }

        const uint32_t base = sbu + ((kb & 1) ? 30720u : 0u);
        const uint32_t aA = base + arow + (uint32_t)wm * 5120u;            // A rows (bytes)
        const uint32_t aB = base + 10240u + arow + (uint32_t)wn * 2560u;   // Bh rows
#pragma unroll
        for (int kh = 0; kh < 2; kh++) {
            const uint32_t ko = (uint32_t)kh * 32u;
            uint32_t ah[4][4], bh[2][4], bl_[2][4];
#pragma unroll
            for (int mi = 0; mi < 4; mi++)
                ldsm4(ah[mi], aA + (uint32_t)mi * 1280u + ko);
#pragma unroll
            for (int nj = 0; nj < 2; nj++) {
                ldsm4(bh[nj],  aB + (uint32_t)nj * 1280u + ko);
                ldsm4(bl_[nj], aB + 10240u + (uint32_t)nj * 1280u + ko);
            }
#pragma unroll
            for (int mi = 0; mi < 4; mi++) {
#pragma unroll
                for (int ni = 0; ni < 4; ni++) {
                    const int nj = ni >> 1, sb_ = ni & 1;
                    mma16816h(acc[mi][ni], ah[mi], bh[nj][sb_],  bh[nj][sb_ + 2]);
                    mma16816h(acc[mi][ni], ah[mi], bl_[nj][sb_], bl_[nj][sb_ + 2]);
                }
            }
        }

        if (pf) {
            __half* d0 = sbase + ((kb + 1) & 1) * 15360;
#pragma unroll
            for (int t2 = 0; t2 < 3; t2++) {
                __half* d = d0 + t2 * 5120;
                *reinterpret_cast<uint4*>(d + r0 * 40 + qq * 8)        = v[t2][0];
                *reinterpret_cast<uint4*>(d + (r0 + 64) * 40 + qq * 8) = v[t2][1];
            }
        }
        __syncthreads();
    }

#pragma unroll
    for (int mi = 0; mi < 4; mi++) {
#pragma unroll
        for (int ni = 0; ni < 4; ni++) {
            const int coll = wn * 32 + ni * 8 + (lane & 3) * 2;
            const int rowa = bm + wm * 64 + mi * 16 + (lane >> 2);
            const float bx = bsum[coll], by = bsum[coll + 1];
            if (rowa < M) {
                float2 p = make_float2(acc[mi][ni][0] + bx, acc[mi][ni][1] + by);
                *reinterpret_cast<float2*>(C + (size_t)rowa * G + bn + coll) = p;
            }
            if (rowa + 8 < M) {
                float2 p = make_float2(acc[mi][ni][2] + bx, acc[mi][ni][3] + by);
                *reinterpret_cast<float2*>(C + (size_t)(rowa + 8) * G + bn + coll) = p;
            }
        }
    }
}

// ---------------- persistent tensor-core LSTM scan (round-12 proven version) ----
// A = h (single fp16), B = w_hh split hi+lo fp16. 1-deep double-buffered A loads.
template<bool L0>
__global__ void __launch_bounds__(256, 1) k_scan_mma() {
    constexpr int NT = 4, NU = 8, NP = 34;
    __shared__ float gd[4][64][NP];
    __shared__ float c_sm[64][NU];

    const int tid = threadIdx.x, wid = tid >> 5, lane = tid & 31;
    const int kh = wid >> 1, mh = wid & 1;
    const int tig = lane & 3, gid = lane >> 2;

    const int cta = blockIdx.x;                  // 0..63
    const int dir = L0 ? blockIdx.y : 0;
    const int rev = L0 ? dir : 0;
    const int jbase = cta * NU;

    const float* gx = L0 ? (g_gx0 + (size_t)dir * TT * Bsz * G) : g_gx1f;
    const uint4* wf4 = L0 ? ((const uint4*)g_wf0) + ((size_t)dir * 64 + cta) * 4096
                          : ((const uint4*)g_wf1) + (size_t)cta * 4096;
    uint32_t* f0 = L0 ? g_f0[dir][0] : g_f1[0];
    uint32_t* f1 = L0 ? g_f0[dir][1] : g_f1[1];
    unsigned* dom = g_flags + (L0 ? dir * 512 : 1024);
    unsigned* flag_me = dom + cta * 8;
    const unsigned* flag_src = dom + (16 * kh + (lane & 15)) * 8;

    for (int i = tid; i < 64 * NU; i += 256) ((float*)c_sm)[i] = 0.f;

    // pointwise role: thread -> (batch pb, unit pair ppi)
    const int pb  = tid >> 2;
    const int ppi = tid & 3;
    const int jg  = jbase + 2 * ppi;
    const int fc = jg & 15, fr = pb & 15, fmt = pb >> 4, fkt = jg >> 4;
    const int flane = ((fr & 7) << 2) | ((fc & 7) >> 1);
    const int freg  = ((fr >> 3) & 1) | (((fc >> 3) & 1) << 1);
    const int faddr = ((fkt * 4 + fmt) * 32 + flane) * 4 + freg;

    __syncthreads();

    for (int t = 0; t < TT; t++) {
        const int tt = rev ? (TT - 1 - t) : t;
        const uint32_t* fin = (t & 1) ? f1 : f0;
        uint32_t* fout = (t & 1) ? f0 : f1;

        // gate pre-activations (independent of h; issued before the wait)
        float2 pre[4];
        {
            const float* gp = gx + ((size_t)tt * Bsz + pb) * G + jg;
            pre[0] = __ldcs((const float2*)gp);
            pre[1] = __ldcs((const float2*)(gp + 512));
            pre[2] = __ldcs((const float2*)(gp + 1024));
            pre[3] = __ldcs((const float2*)(gp + 1536));
        }

        // wait for this warp's producers to have published h^t
        if (t > 0) {
            unsigned v;
            do {
                asm volatile("ld.acquire.gpu.global.u32 %0, [%1];"
                             : "=r"(v) : "l"(flag_src) : "memory");
            } while (v < (unsigned)t);
            __syncwarp();
        }

        float acc[2][NT][4];
#pragma unroll
        for (int m2 = 0; m2 < 2; m2++)
#pragma unroll
            for (int nt = 0; nt < NT; nt++)
#pragma unroll
                for (int r = 0; r < 4; r++) acc[m2][nt][r] = 0.f;

        // A-fragment double buffer (single fp16 term: one uint4 per slot)
        uint4 cA[2];
        {
            const int kt0 = kh * 8;
#pragma unroll
            for (int m2 = 0; m2 < 2; m2++) {
                const uint32_t* ap = fin + ((size_t)(kt0 * 4 + mh * 2 + m2) * 32 + lane) * 4;
                cA[m2] = __ldcg((const uint4*)ap);
            }
        }

#pragma unroll
        for (int k8 = 0; k8 < 8; k8++) {
            const int kt = kh * 8 + k8;
            uint4 nA[2];
            if (k8 < 7) {
#pragma unroll
                for (int m2 = 0; m2 < 2; m2++) {
                    const uint32_t* ap = fin + ((size_t)((kt + 1) * 4 + mh * 2 + m2) * 32 + lane) * 4;
                    nA[m2] = __ldcg((const uint4*)ap);
                }
            }
            uint4 Bv[NT];
#pragma unroll
            for (int nt = 0; nt < NT; nt++)
                Bv[nt] = __ldg(wf4 + (size_t)(kt * NT + nt) * 32 + lane);
#pragma unroll
            for (int m2 = 0; m2 < 2; m2++) {
                uint32_t a[4] = {cA[m2].x, cA[m2].y, cA[m2].z, cA[m2].w};
#pragma unroll
                for (int nt = 0; nt < NT; nt++) {
                    mma16816h(acc[m2][nt], a, Bv[nt].x, Bv[nt].y);   // h * w_hi
                    mma16816h(acc[m2][nt], a, Bv[nt].z, Bv[nt].w);   // h * w_lo
                }
            }
            if (k8 < 7) {
#pragma unroll
                for (int m2 = 0; m2 < 2; m2++) cA[m2] = nA[m2];
            }
        }

        // dump K-quarter partials to smem
#pragma unroll
        for (int m2 = 0; m2 < 2; m2++) {
            const int rb = (mh * 2 + m2) * 16 + gid;
#pragma unroll
            for (int nt = 0; nt < NT; nt++) {
                const int col = nt * 8 + tig * 2;
                *(float2*)&gd[kh][rb][col]     = make_float2(acc[m2][nt][0], acc[m2][nt][1]);
                *(float2*)&gd[kh][rb + 8][col] = make_float2(acc[m2][nt][2], acc[m2][nt][3]);
            }
        }
        __syncthreads();

        // pointwise + h publish (fp16 pair: one word)
        float hv[2];
        uint32_t hpk;
        {
#pragma unroll
            for (int uu = 0; uu < 2; uu++) {
                const int u = 2 * ppi + uu;
                float gi = uu ? pre[0].y : pre[0].x;
                float gf = uu ? pre[1].y : pre[1].x;
                float gc = uu ? pre[2].y : pre[2].x;
                float go = uu ? pre[3].y : pre[3].x;
#pragma unroll
                for (int q = 0; q < 4; q++) {
                    gi += gd[q][pb][0 * NU + u];
                    gf += gd[q][pb][1 * NU + u];
                    gc += gd[q][pb][2 * NU + u];
                    go += gd[q][pb][3 * NU + u];
                }
                float cc = sigf(gf) * c_sm[pb][u] + sigf(gi) * tanhfast(gc);
                float hh = sigf(go) * tanhfast(cc);
                c_sm[pb][u] = cc;
                hv[uu] = hh;
            }
            __half2 hp = __floats2half2_rn(hv[0], hv[1]);
            hpk = *reinterpret_cast<uint32_t*>(&hp);
            __stcg((unsigned int*)&fout[faddr], hpk);
        }
        __syncthreads();
        if (tid == 0) {
            asm volatile("st.release.gpu.global.u32 [%0], %1;"
                         :: "l"(flag_me), "r"((unsigned)(t + 1)) : "memory");
        }

        // side outputs off the critical path (single fp16 word now)
        if (L0) {
            const size_t oo = ((size_t)tt * Bsz + pb) * (2 * Hh) + (size_t)dir * Hh + jg;
            __stcg((unsigned int*)&g_o0h[oo], hpk);
        } else {
            g_h1f[(size_t)pb * Hh + jg]     = hv[0];
            g_h1f[(size_t)pb * Hh + jg + 1] = hv[1];
        }
    }
}

// layer1 backward at t=T-1: first step of reverse scan from zero state
__global__ void k_l1bwd() {
    int i = blockIdx.x * 256 + threadIdx.x;
    int b = i >> 9, j = i & 511;
    const float* gxp = g_gx1b + b * G;
    float gi = gxp[j], gc = gxp[2 * Hh + j], go = gxp[3 * Hh + j];
    float c = sigf(gi) * tanhfast(gc);
    float h = sigf(go) * tanhfast(c);
    g_hb[b * Hh + j] = h;
}

// ---------------- layernorm + MLP head ----------------
__global__ void __launch_bounds__(256) k_head(
    const float* __restrict__ ln_g, const float* __restrict__ ln_b,
    const float* __restrict__ w1,   const float* __restrict__ b1,
    const float* __restrict__ w2,   const float* __restrict__ b2,
    float* __restrict__ out)
{
    int b = blockIdx.x, tid = threadIdx.x;
    __shared__ float v[1024];
    __shared__ float red[256];
    for (int i = tid; i < Hh; i += 256) {
        v[i]      = g_h1f[b * Hh + i];
        v[Hh + i] = g_hb[b * Hh + i];
    }
    __syncthreads();
    float s = 0.f;
    for (int i = tid; i < 1024; i += 256) s += v[i];
    red[tid] = s; __syncthreads();
    for (int st = 128; st > 0; st >>= 1) { if (tid < st) red[tid] += red[tid + st]; __syncthreads(); }
    float mu = red[0] * (1.0f / 1024.0f);
    __syncthreads();
    s = 0.f;
    for (int i = tid; i < 1024; i += 256) { float dd = v[i] - mu; s += dd * dd; }
    red[tid] = s; __syncthreads();
    for (int st = 128; st > 0; st >>= 1) { if (tid < st) red[tid] += red[tid + st]; __syncthreads(); }
    float rstd = rsqrtf(red[0] * (1.0f / 1024.0f) + 1e-5f);
    __syncthreads();
    for (int i = tid; i < 1024; i += 256) v[i] = (v[i] - mu) * rstd * ln_g[i] + ln_b[i];
    __syncthreads();
    float part = 0.f;
    for (int jj = tid; jj < Hh; jj += 256) {
        float acc = b1[jj];
        const float* wr = w1 + (size_t)jj * 1024;
#pragma unroll 4
        for (int k2 = 0; k2 < 1024; k2++) acc += v[k2] * wr[k2];
        part += fmaxf(acc, 0.f) * w2[jj];
    }
    red[tid] = part; __syncthreads();
    for (int st = 128; st > 0; st >>= 1) { if (tid < st) red[tid] += red[tid + st]; __syncthreads(); }
    if (tid == 0) out[b] = red[0] + b2[0];
}

// ---------------- launch ----------------
extern "C" void kernel_launch(void* const* d_in, const int* in_sizes, int n_in,
                              void* d_out, int out_size)
{
    (void)in_sizes; (void)n_in; (void)out_size;
    const float* x     = (const float*)d_in[0];
    const float* w_ih0 = (const float*)d_in[1];
    const float* w_hh0 = (const float*)d_in[2];
    const float* b_ih0 = (const float*)d_in[3];
    const float* b_hh0 = (const float*)d_in[4];
    const float* w_ih1 = (const float*)d_in[5];
    const float* w_hh1 = (const float*)d_in[6];
    const float* b_ih1 = (const float*)d_in[7];
    const float* b_hh1 = (const float*)d_in[8];
    const float* ln_g  = (const float*)d_in[9];
    const float* ln_b  = (const float*)d_in[10];
    const float* w1    = (const float*)d_in[11];
    const float* b1    = (const float*)d_in[12];
    const float* w2    = (const float*)d_in[13];
    const float* b2    = (const float*)d_in[14];
    float* out = (float*)d_out;

    cudaFuncSetAttribute(k_mma_gemm, cudaFuncAttributeMaxDynamicSharedMemorySize, MMSM);

    void *p_gx0, *p_gx1f, *p_gx1b;
    void *p_xh, *p_o0h, *p_w0h, *p_w0l, *p_w1h, *p_w1l;
    cudaGetSymbolAddress(&p_gx0, g_gx0);
    cudaGetSymbolAddress(&p_gx1f, g_gx1f);
    cudaGetSymbolAddress(&p_gx1b, g_gx1b);
    cudaGetSymbolAddress(&p_xh, g_xh);
    cudaGetSymbolAddress(&p_o0h, g_o0h);
    cudaGetSymbolAddress(&p_w0h, g_w0h); cudaGetSymbolAddress(&p_w0l, g_w0l);
    cudaGetSymbolAddress(&p_w1h, g_w1h); cudaGetSymbolAddress(&p_w1l, g_w1l);

    // our launch #3 (0-based) is what ncu -s 5 profiles (2 harness kernels first)
    k_prep0<<<41472, 256>>>(x, w_ih0, w_hh0);                            // 0

    // layer 0 input projections, both directions via gridDim.z=2
    k_mma_gemm<<<dim3(16, 256, 2), 256, MMSM>>>(                         // 1
        (__half*)p_xh, (__half*)p_w0h, (__half*)p_w0l,
        b_ih0, b_hh0, (float*)p_gx0, Bsz * TT, Din,
        (size_t)G * Din, (size_t)TT * Bsz * G, G);

    k_prep1<<<18432, 256>>>(w_ih1, w_hh1);                               // 2

    // layer 0 bidirectional scan  <- profiled
    k_scan_mma<true><<<dim3(64, 2), 256>>>();                            // 3

    // layer 1 fwd projection + bwd projection (only t = T-1)
    k_mma_gemm<<<dim3(16, 256, 1), 256, MMSM>>>(                         // 4
        (__half*)p_o0h, (__half*)p_w1h, (__half*)p_w1l,
        b_ih1, b_hh1, (float*)p_gx1f, Bsz * TT, 2 * Hh, 0, 0, 0);
    k_mma_gemm<<<dim3(16, 1, 1), 256, MMSM>>>(                           // 5
        (__half*)p_o0h + (size_t)(TT - 1) * Bsz * 2 * Hh,
        (__half*)p_w1h + (size_t)G * 2 * Hh, (__half*)p_w1l + (size_t)G * 2 * Hh,
        b_ih1 + G, b_hh1 + G, (float*)p_gx1b, Bsz, 2 * Hh, 0, 0, 0);

    // layer 1 forward scan (64 CTAs, NU=8)
    k_scan_mma<false><<<64, 256>>>();                                    // 6

    k_l1bwd<<<128, 256>>>();                                             // 7
    k_head<<<64, 256>>>(ln_g, ln_b, w1, b1, w2, b2, out);                // 8
}

// round 17
// speedup vs baseline: 1.4239x; 1.1217x over previous
#include <cuda_runtime.h>
#include <cuda_bf16.h>
#include <cuda_fp16.h>
#include <cstdint>
#include <math.h>

#define Bsz 64
#define TT  512
#define Din 256
#define Hh  512
#define G   2048   /* 4*H */

typedef unsigned long long ull;

// ---------------- scratch (static device globals; no allocation) ----------------
__device__ float g_gx1b[Bsz*G];                 // layer1 bwd preacts at t=T-1
__device__ float g_h1f[Bsz*Hh];                 // layer1 fwd h (final used)
__device__ float g_hb[Bsz*Hh];                  // layer1 bwd one-step hidden
__device__ unsigned g_flags[3*64*8];            // per-CTA step flags, 32B padded

// A-fragment fp16 inputs for the fused scans
__device__ uint32_t g_xf [(size_t)TT*8192];     // x frags [t][kt16][mt4][lane32][reg4] 16MB
__device__ uint32_t g_o0f[(size_t)TT*32768];    // o0 frags [t][kt64][mt4][lane32][reg4] 64MB
__device__ __half   g_o0last[Bsz*2*Hh];         // o0[T-1] linear (for bwd projection)
// W_ih B-fragments (fp16 hi/lo), per CTA slice
__device__ uint32_t g_wi0f[2*64*8192];          // [dir][cta]: [kt16][nt4][lane32][4]
__device__ uint32_t g_wi1f[64*32768];           // dir0: [cta][kt64][nt4][lane32][4]
// linear fp16 hi/lo of w_ih1 dir1 (bwd projection GEMM operand)
__device__ __half g_w1h[(size_t)G*2*Hh], g_w1l[(size_t)G*2*Hh];

// h state in MMA A-fragment layout (fp16): [kt32][mt4][lane32][reg4]
__device__ uint32_t g_f0[2][2][16384];          // [dir][pingpong]
__device__ uint32_t g_f1[2][16384];             // layer1 fwd [pingpong]
// W_hh B-fragments (fp16 hi/lo), 16384 words per CTA: [kt32][nt4][lane32][4]
__device__ uint32_t g_wf0[2*64*16384];          // [dir][cta]
__device__ uint32_t g_wf1[64*16384];            // [cta]

__device__ __forceinline__ float sigf(float x) { return 1.0f / (1.0f + __expf(-x)); }
__device__ __forceinline__ float tanhfast(float x) {
    float e = __expf(-2.0f * fabsf(x));
    float r = (1.0f - e) / (1.0f + e);
    return copysignf(r, x);
}

// ---------------- mma.sync helpers ----------------
__device__ __forceinline__ uint32_t smem_u32(const void* p) {
    uint32_t a;
    asm("{ .reg .u64 t; cvta.to.shared.u64 t, %1; cvt.u32.u64 %0, t; }" : "=r"(a) : "l"(p));
    return a;
}
__device__ __forceinline__ void ldsm4(uint32_t* r, uint32_t addr) {
    asm volatile("ldmatrix.sync.aligned.m8n8.x4.shared.b16 {%0,%1,%2,%3}, [%4];"
                 : "=r"(r[0]), "=r"(r[1]), "=r"(r[2]), "=r"(r[3]) : "r"(addr));
}
__device__ __forceinline__ void mma16816h(float* d, const uint32_t* a,
                                          uint32_t b0, uint32_t b1) {
    asm volatile(
        "mma.sync.aligned.m16n8k16.row.col.f32.f16.f16.f32 "
        "{%0,%1,%2,%3}, {%4,%5,%6,%7}, {%8,%9}, {%0,%1,%2,%3};"
        : "+f"(d[0]), "+f"(d[1]), "+f"(d[2]), "+f"(d[3])
        : "r"(a[0]), "r"(a[1]), "r"(a[2]), "r"(a[3]), "r"(b0), "r"(b1));
}

// ---------------- pack helpers ----------------
__device__ __forceinline__ void wfrag_pack_h(float wx, float wy, uint32_t& whi, uint32_t& wlo) {
    __half h0 = __float2half_rn(wx), h1 = __float2half_rn(wy);
    __half l0 = __float2half_rn(wx - __half2float(h0));
    __half l1 = __float2half_rn(wy - __half2float(h1));
    whi = (uint32_t)__half_as_ushort(h0) | ((uint32_t)__half_as_ushort(h1) << 16);
    wlo = (uint32_t)__half_as_ushort(l0) | ((uint32_t)__half_as_ushort(l1) << 16);
}
__device__ __forceinline__ uint32_t pack2h(float a, float b) {
    __half2 hp = __floats2half2_rn(a, b);
    return *reinterpret_cast<uint32_t*>(&hp);
}

// ---------------- prepx: x[b][t][d] fp32 -> A-fragment fp16 [t]... ----------------
__global__ void k_prepx(const float* __restrict__ x) {
    int i = blockIdx.x * 256 + threadIdx.x;          // 4,194,304 pairs
    int dp = i & 127, b = (i >> 7) & 63, t = i >> 13;
    int d = dp * 2;
    const float* s = x + ((size_t)b * TT + t) * Din + d;
    uint32_t w = pack2h(s[0], s[1]);
    int kt = d >> 4, col = d & 15, mt = b >> 4;
    int lane = ((b & 7) << 2) | ((col & 7) >> 1);
    int reg  = ((b >> 3) & 1) | (((col >> 3) & 1) << 1);
    g_xf[(size_t)t * 8192 + ((size_t)(kt * 4 + mt) * 32 + lane) * 4 + reg] = w;
}

// ---------------- prepw: w_ih0 B-frags + w_hh0 B-frags + state/flag init --------
__global__ void k_prepw(const float* __restrict__ w_ih0, const float* __restrict__ w_hh0) {
    const int blk = blockIdx.x, tid = threadIdx.x;
    if (blk < 2048) {                                // w_ih0 frag: 524288 pairs
        int idx = blk * 256 + tid;
        int dp = idx & 127, r = (idx >> 7) & 2047, d = idx >> 18;
        int k = dp * 2;
        int gg = r >> 9, jj = r & 511;
        int cta = jj >> 3, u = jj & 7;
        int ngl = gg * 8 + u, nt = ngl >> 3, nc = ngl & 7;
        int kt = k >> 4;
        int lane = (nc << 2) | ((k & 7) >> 1);
        int reg = ((k & 15) >= 8) ? 1 : 0;
        float2 wv = *(const float2*)(w_ih0 + ((size_t)d * G + r) * Din + k);
        uint32_t whi, wlo; wfrag_pack_h(wv.x, wv.y, whi, wlo);
        size_t base = ((size_t)d * 64 + cta) * 8192 + ((size_t)(kt * 4 + nt) * 32 + lane) * 4;
        g_wi0f[base + reg]     = whi;
        g_wi0f[base + reg + 2] = wlo;
    } else if (blk < 6144) {                         // w_hh0 frag: < 1048576
        int idx = (blk - 2048) * 256 + tid;
        int d  = idx >> 19;
        int r  = (idx >> 8) & 2047;
        int k  = (idx & 255) * 2;
        int gg = r >> 9, jj = r & 511;
        int cta = jj >> 3, u = jj & 7;
        int ngl = gg * 8 + u, nt = ngl >> 3, nc = ngl & 7;
        int kt = k >> 4;
        int lane = (nc << 2) | ((k & 7) >> 1);
        int reg = ((k & 15) >= 8) ? 1 : 0;
        float2 wv = *(const float2*)(w_hh0 + ((size_t)d * G + r) * Hh + k);
        uint32_t whi, wlo; wfrag_pack_h(wv.x, wv.y, whi, wlo);
        size_t base = ((size_t)d * 64 + cta) * 16384 + ((size_t)(kt * 4 + nt) * 32 + lane) * 4;
        g_wf0[base + reg]     = whi;
        g_wf0[base + reg + 2] = wlo;
    } else {                                         // state + flag init (512 blocks)
        int i = (blk - 6144) * 256 + tid;            // < 131072
        if (i < 65536) (&g_f0[0][0][0])[i] = 0u;
        if (i < 32768) (&g_f1[0][0])[i]    = 0u;
        if (i < 3*64*8) g_flags[i] = 0u;
    }
}

// ---------------- prep1: w_ih1 dir1 linear hi/lo + w_ih1 dir0 frag + w_hh1 frag --
__global__ void k_prep1(const float* __restrict__ w_ih1, const float* __restrict__ w_hh1) {
    const int blk = blockIdx.x, tid = threadIdx.x;
    if (blk < 8192) {                                // w_ih1 dir1 linear split (2M elems)
        int i = blk * 256 + tid;
        float v = w_ih1[(size_t)G * 2 * Hh + i];
        __half h = __float2half_rn(v);
        g_w1h[i] = h;
        g_w1l[i] = __float2half_rn(v - __half2float(h));
    } else if (blk < 12288) {                        // w_ih1 dir0 frag: 1048576 pairs
        int idx = (blk - 8192) * 256 + tid;
        int dp = idx & 511, r = idx >> 9;
        int k = dp * 2;
        int gg = r >> 9, jj = r & 511;
        int cta = jj >> 3, u = jj & 7;
        int ngl = gg * 8 + u, nt = ngl >> 3, nc = ngl & 7;
        int kt = k >> 4;
        int lane = (nc << 2) | ((k & 7) >> 1);
        int reg = ((k & 15) >= 8) ? 1 : 0;
        float2 wv = *(const float2*)(w_ih1 + (size_t)r * 2 * Hh + k);
        uint32_t whi, wlo; wfrag_pack_h(wv.x, wv.y, whi, wlo);
        size_t base = (size_t)cta * 32768 + ((size_t)(kt * 4 + nt) * 32 + lane) * 4;
        g_wi1f[base + reg]     = whi;
        g_wi1f[base + reg + 2] = wlo;
    } else {                                         // w_hh1 frag: < 524288
        int idx = (blk - 12288) * 256 + tid;
        int r  = idx >> 8;
        int k  = (idx & 255) * 2;
        int gg = r >> 9, jj = r & 511;
        int cta = jj >> 3, u = jj & 7;
        int ngl = gg * 8 + u, nt = ngl >> 3, nc = ngl & 7;
        int kt = k >> 4;
        int lane = (nc << 2) | ((k & 7) >> 1);
        int reg = ((k & 15) >= 8) ? 1 : 0;
        float2 wv = *(const float2*)(w_hh1 + (size_t)r * Hh + k);
        uint32_t whi, wlo; wfrag_pack_h(wv.x, wv.y, whi, wlo);
        size_t base = (size_t)cta * 16384 + ((size_t)(kt * 4 + nt) * 32 + lane) * 4;
        g_wf1[base + reg]     = whi;
        g_wf1[base + reg + 2] = wlo;
    }
}

// ---------------- HMMA fp16 GEMM (bwd projection only): A fp16, B hi+lo fp16 ----
#define MMSM (2 * 3 * 128 * 40 * 2 + 512)

__device__ __forceinline__ uint4 g_ld4h(const __half* __restrict__ src, int K,
                                        int row, int k0, int q, int rowsv) {
    if (row < rowsv)
        return *reinterpret_cast<const uint4*>(src + (size_t)row * K + k0 + q * 8);
    return make_uint4(0u, 0u, 0u, 0u);
}

__global__ void __launch_bounds__(256) k_mma_gemm(
    const __half* __restrict__ A,
    const __half* __restrict__ Bh, const __half* __restrict__ Bl,
    const float* __restrict__ bia, const float* __restrict__ bib,
    float* __restrict__ C, int M, int K)
{
    extern __shared__ __align__(16) char smx[];
    __half* sbase = (__half*)smx;
    float*  bsum  = (float*)(smx + 61440);
    const int tid = threadIdx.x, wid = tid >> 5, lane = tid & 31;
    const int bn = blockIdx.x << 7, bm = blockIdx.y << 7;
    const int wm = wid >> 2, wn = wid & 3;
    const int av = (M - bm < 128) ? (M - bm) : 128;

    if (tid < 128) bsum[tid] = bia[bn + tid] + bib[bn + tid];

    const __half* gA  = A  + (size_t)bm * K;
    const __half* gBh = Bh + (size_t)bn * K;
    const __half* gBl = Bl + (size_t)bn * K;

    const int r0 = tid >> 2, qq = tid & 3;

    {
        uint4 v[3][2];
        v[0][0] = g_ld4h(gA,  K, r0, 0, qq, av);  v[0][1] = g_ld4h(gA,  K, r0+64, 0, qq, av);
        v[1][0] = g_ld4h(gBh, K, r0, 0, qq, 128); v[1][1] = g_ld4h(gBh, K, r0+64, 0, qq, 128);
        v[2][0] = g_ld4h(gBl, K, r0, 0, qq, 128); v[2][1] = g_ld4h(gBl, K, r0+64, 0, qq, 128);
#pragma unroll
        for (int t2 = 0; t2 < 3; t2++) {
            __half* d = sbase + t2 * 5120;
            *reinterpret_cast<uint4*>(d + r0 * 40 + qq * 8)        = v[t2][0];
            *reinterpret_cast<uint4*>(d + (r0 + 64) * 40 + qq * 8) = v[t2][1];
        }
    }
    __syncthreads();

    float acc[4][4][4];
#pragma unroll
    for (int mi = 0; mi < 4; mi++)
#pragma unroll
        for (int ni = 0; ni < 4; ni++)
#pragma unroll
            for (int r = 0; r < 4; r++) acc[mi][ni][r] = 0.0f;

    const uint32_t sbu  = smem_u32(sbase);
    const uint32_t arow = 2u * (((uint32_t)(lane & 15)) * 40u + ((uint32_t)(lane >> 4)) * 8u);
    const int NKB = K >> 5;

    for (int kb = 0; kb < NKB; kb++) {
        uint4 v[3][2];
        const bool pf = (kb + 1 < NKB);
        if (pf) {
            const int k0 = (kb + 1) << 5;
            v[0][0] = g_ld4h(gA,  K, r0, k0, qq, av);  v[0][1] = g_ld4h(gA,  K, r0+64, k0, qq, av);
            v[1][0] = g_ld4h(gBh, K, r0, k0, qq, 128); v[1][1] = g_ld4h(gBh, K, r0+64, k0, qq, 128);
            v[2][0] = g_ld4h(gBl, K, r0, k0, qq, 128); v[2][1] = g_ld4h(gBl, K, r0+64, k0, qq, 128);
        }

        const uint32_t base = sbu + ((kb & 1) ? 30720u : 0u);
        const uint32_t aA = base + arow + (uint32_t)wm * 5120u;
        const uint32_t aB = base + 10240u + arow + (uint32_t)wn * 2560u;
#pragma unroll
        for (int kh = 0; kh < 2; kh++) {
            const uint32_t ko = (uint32_t)kh * 32u;
            uint32_t ah[4][4], bh[2][4], bl_[2][4];
#pragma unroll
            for (int mi = 0; mi < 4; mi++)
                ldsm4(ah[mi], aA + (uint32_t)mi * 1280u + ko);
#pragma unroll
            for (int nj = 0; nj < 2; nj++) {
                ldsm4(bh[nj],  aB + (uint32_t)nj * 1280u + ko);
                ldsm4(bl_[nj], aB + 10240u + (uint32_t)nj * 1280u + ko);
            }
#pragma unroll
            for (int mi = 0; mi < 4; mi++) {
#pragma unroll
                for (int ni = 0; ni < 4; ni++) {
                    const int nj = ni >> 1, sb_ = ni & 1;
                    mma16816h(acc[mi][ni], ah[mi], bh[nj][sb_],  bh[nj][sb_ + 2]);
                    mma16816h(acc[mi][ni], ah[mi], bl_[nj][sb_], bl_[nj][sb_ + 2]);
                }
            }
        }

        if (pf) {
            __half* d0 = sbase + ((kb + 1) & 1) * 15360;
#pragma unroll
            for (int t2 = 0; t2 < 3; t2++) {
                __half* d = d0 + t2 * 5120;
                *reinterpret_cast<uint4*>(d + r0 * 40 + qq * 8)        = v[t2][0];
                *reinterpret_cast<uint4*>(d + (r0 + 64) * 40 + qq * 8) = v[t2][1];
            }
        }
        __syncthreads();
    }

#pragma unroll
    for (int mi = 0; mi < 4; mi++) {
#pragma unroll
        for (int ni = 0; ni < 4; ni++) {
            const int coll = wn * 32 + ni * 8 + (lane & 3) * 2;
            const int rowa = bm + wm * 64 + mi * 16 + (lane >> 2);
            const float bx = bsum[coll], by = bsum[coll + 1];
            if (rowa < M) {
                float2 p = make_float2(acc[mi][ni][0] + bx, acc[mi][ni][1] + by);
                *reinterpret_cast<float2*>(C + (size_t)rowa * G + bn + coll) = p;
            }
            if (rowa + 8 < M) {
                float2 p = make_float2(acc[mi][ni][2] + bx, acc[mi][ni][3] + by);
                *reinterpret_cast<float2*>(C + (size_t)(rowa + 8) * G + bn + coll) = p;
            }
        }
    }
}

// ---------------- fused persistent scan: gates = x@Wih^T + h@Whh^T + b ----------
// x-part MMAs (no h dependency) execute BEFORE the flag wait -> fill the latency
// window. x / o0 pre-packed as A-fragments; W_ih/W_hh as per-CTA B-fragments.
template<bool L0>
__global__ void __launch_bounds__(256, 1) k_scan_mma(
    const float* __restrict__ bih, const float* __restrict__ bhh)
{
    constexpr int NT = 4, NU = 8, NP = 34;
    constexpr int KTXW = L0 ? 4 : 16;            // x-part kt per warp
    constexpr int SX   = L0 ? 8192 : 32768;      // x-frag words per t
    __shared__ float gd[4][64][NP];
    __shared__ float c_sm[64][NU];

    const int tid = threadIdx.x, wid = tid >> 5, lane = tid & 31;
    const int kh = wid >> 1, mh = wid & 1;
    const int tig = lane & 3, gid = lane >> 2;

    const int cta = blockIdx.x;                  // 0..63
    const int dir = L0 ? blockIdx.y : 0;
    const int rev = L0 ? dir : 0;
    const int jbase = cta * NU;

    const uint32_t* xf = L0 ? g_xf : g_o0f;
    const uint4* wi4 = L0 ? ((const uint4*)g_wi0f) + ((size_t)(dir * 64 + cta) * 2048)
                          : ((const uint4*)g_wi1f) + (size_t)cta * 8192;
    const uint4* wf4 = L0 ? ((const uint4*)g_wf0) + ((size_t)(dir * 64 + cta) * 4096)
                          : ((const uint4*)g_wf1) + (size_t)cta * 4096;
    uint32_t* f0 = L0 ? g_f0[dir][0] : g_f1[0];
    uint32_t* f1 = L0 ? g_f0[dir][1] : g_f1[1];
    unsigned* dom = g_flags + (L0 ? dir * 512 : 1024);
    unsigned* flag_me = dom + cta * 8;
    const unsigned* flag_src = dom + (16 * kh + (lane & 15)) * 8;

    for (int i = tid; i < 64 * NU; i += 256) ((float*)c_sm)[i] = 0.f;

    // pointwise role: thread -> (batch pb, unit pair ppi)
    const int pb  = tid >> 2;
    const int ppi = tid & 3;
    const int jg  = jbase + 2 * ppi;
    const int fc = jg & 15, fr = pb & 15, fmt = pb >> 4, fkt = jg >> 4;
    const int flane = ((fr & 7) << 2) | ((fc & 7) >> 1);
    const int freg  = ((fr >> 3) & 1) | (((fc >> 3) & 1) << 1);
    const int faddr = ((fkt * 4 + fmt) * 32 + flane) * 4 + freg;

    // biases (b_ih + b_hh), per-unit pair, fp32 in registers
    const float* bi = bih + (L0 ? dir * G : 0);
    const float* bh_ = bhh + (L0 ? dir * G : 0);
    float bs[4][2];
#pragma unroll
    for (int g = 0; g < 4; g++) {
        bs[g][0] = bi[g * Hh + jg]     + bh_[g * Hh + jg];
        bs[g][1] = bi[g * Hh + jg + 1] + bh_[g * Hh + jg + 1];
    }

    // o0 A-frag output slot (L0 only): k index = dir*512 + jg
    const int ko = dir * Hh + jg;
    const int kto = ko >> 4, colo = ko & 15;
    const int lane_o = ((pb & 7) << 2) | ((colo & 7) >> 1);
    const int reg_o  = ((pb >> 3) & 1) | (((colo >> 3) & 1) << 1);
    const int o_off  = ((kto * 4 + (pb >> 4)) * 32 + lane_o) * 4 + reg_o;

    __syncthreads();

    for (int t = 0; t < TT; t++) {
        const int tt = rev ? (TT - 1 - t) : t;
        const uint32_t* fin = (t & 1) ? f1 : f0;
        uint32_t* fout = (t & 1) ? f0 : f1;

        float acc[2][NT][4];
#pragma unroll
        for (int m2 = 0; m2 < 2; m2++)
#pragma unroll
            for (int nt = 0; nt < NT; nt++)
#pragma unroll
                for (int r = 0; r < 4; r++) acc[m2][nt][r] = 0.f;

        // ---- x-part (independent of h): fills the wait window ----
        {
            const uint32_t* xft = xf + (size_t)tt * SX;
#pragma unroll 4
            for (int i = 0; i < KTXW; i++) {
                const int ktx = kh * KTXW + i;
                uint4 Ax[2];
#pragma unroll
                for (int m2 = 0; m2 < 2; m2++)
                    Ax[m2] = __ldcg((const uint4*)
                        (xft + ((size_t)(ktx * 4 + mh * 2 + m2) * 32 + lane) * 4));
#pragma unroll
                for (int nt = 0; nt < NT; nt++) {
                    uint4 Bx = __ldg(wi4 + (size_t)(ktx * 4 + nt) * 32 + lane);
#pragma unroll
                    for (int m2 = 0; m2 < 2; m2++) {
                        uint32_t a[4] = {Ax[m2].x, Ax[m2].y, Ax[m2].z, Ax[m2].w};
                        mma16816h(acc[m2][nt], a, Bx.x, Bx.y);   // x * wih_hi
                        mma16816h(acc[m2][nt], a, Bx.z, Bx.w);   // x * wih_lo
                    }
                }
            }
        }

        // ---- wait for producers' h^t ----
        if (t > 0) {
            unsigned v;
            do {
                asm volatile("ld.acquire.gpu.global.u32 %0, [%1];"
                             : "=r"(v) : "l"(flag_src) : "memory");
            } while (v < (unsigned)t);
            __syncwarp();
        }

        // ---- recurrent part (double-buffered A loads) ----
        uint4 cA[2];
        {
            const int kt0 = kh * 8;
#pragma unroll
            for (int m2 = 0; m2 < 2; m2++)
                cA[m2] = __ldcg((const uint4*)
                    (fin + ((size_t)(kt0 * 4 + mh * 2 + m2) * 32 + lane) * 4));
        }
#pragma unroll
        for (int k8 = 0; k8 < 8; k8++) {
            const int kt = kh * 8 + k8;
            uint4 nA[2];
            if (k8 < 7) {
#pragma unroll
                for (int m2 = 0; m2 < 2; m2++)
                    nA[m2] = __ldcg((const uint4*)
                        (fin + ((size_t)((kt + 1) * 4 + mh * 2 + m2) * 32 + lane) * 4));
            }
            uint4 Bv[NT];
#pragma unroll
            for (int nt = 0; nt < NT; nt++)
                Bv[nt] = __ldg(wf4 + (size_t)(kt * NT + nt) * 32 + lane);
#pragma unroll
            for (int m2 = 0; m2 < 2; m2++) {
                uint32_t a[4] = {cA[m2].x, cA[m2].y, cA[m2].z, cA[m2].w};
#pragma unroll
                for (int nt = 0; nt < NT; nt++) {
                    mma16816h(acc[m2][nt], a, Bv[nt].x, Bv[nt].y);   // h * whh_hi
                    mma16816h(acc[m2][nt], a, Bv[nt].z, Bv[nt].w);   // h * whh_lo
                }
            }
            if (k8 < 7) {
#pragma unroll
                for (int m2 = 0; m2 < 2; m2++) cA[m2] = nA[m2];
            }
        }

        // dump K-quarter partials to smem
#pragma unroll
        for (int m2 = 0; m2 < 2; m2++) {
            const int rb = (mh * 2 + m2) * 16 + gid;
#pragma unroll
            for (int nt = 0; nt < NT; nt++) {
                const int col = nt * 8 + tig * 2;
                *(float2*)&gd[kh][rb][col]     = make_float2(acc[m2][nt][0], acc[m2][nt][1]);
                *(float2*)&gd[kh][rb + 8][col] = make_float2(acc[m2][nt][2], acc[m2][nt][3]);
            }
        }
        __syncthreads();

        // pointwise + h publish
        float hv[2];
        uint32_t hpk;
        {
#pragma unroll
            for (int uu = 0; uu < 2; uu++) {
                const int u = 2 * ppi + uu;
                float gi = bs[0][uu];
                float gf = bs[1][uu];
                float gc = bs[2][uu];
                float go = bs[3][uu];
#pragma unroll
                for (int q = 0; q < 4; q++) {
                    gi += gd[q][pb][0 * NU + u];
                    gf += gd[q][pb][1 * NU + u];
                    gc += gd[q][pb][2 * NU + u];
                    go += gd[q][pb][3 * NU + u];
                }
                float cc = sigf(gf) * c_sm[pb][u] + sigf(gi) * tanhfast(gc);
                float hh = sigf(go) * tanhfast(cc);
                c_sm[pb][u] = cc;
                hv[uu] = hh;
            }
            hpk = pack2h(hv[0], hv[1]);
            __stcg((unsigned int*)&fout[faddr], hpk);
        }
        __syncthreads();
        if (tid == 0) {
            asm volatile("st.release.gpu.global.u32 [%0], %1;"
                         :: "l"(flag_me), "r"((unsigned)(t + 1)) : "memory");
        }

        // side outputs off the critical path
        if (L0) {
            __stcg((unsigned int*)&g_o0f[(size_t)tt * 32768 + o_off], hpk);
            if (tt == TT - 1)
                ((unsigned int*)g_o0last)[(pb * 2 * Hh + ko) >> 1] = hpk;
        } else {
            g_h1f[(size_t)pb * Hh + jg]     = hv[0];
            g_h1f[(size_t)pb * Hh + jg + 1] = hv[1];
        }
    }
}

// layer1 backward at t=T-1: first step of reverse scan from zero state
__global__ void k_l1bwd() {
    int i = blockIdx.x * 256 + threadIdx.x;
    int b = i >> 9, j = i & 511;
    const float* gxp = g_gx1b + b * G;
    float gi = gxp[j], gc = gxp[2 * Hh + j], go = gxp[3 * Hh + j];
    float c = sigf(gi) * tanhfast(gc);
    float h = sigf(go) * tanhfast(c);
    g_hb[b * Hh + j] = h;
}

// ---------------- layernorm + MLP head ----------------
__global__ void __launch_bounds__(256) k_head(
    const float* __restrict__ ln_g, const float* __restrict__ ln_b,
    const float* __restrict__ w1,   const float* __restrict__ b1,
    const float* __restrict__ w2,   const float* __restrict__ b2,
    float* __restrict__ out)
{
    int b = blockIdx.x, tid = threadIdx.x;
    __shared__ float v[1024];
    __shared__ float red[256];
    for (int i = tid; i < Hh; i += 256) {
        v[i]      = g_h1f[b * Hh + i];
        v[Hh + i] = g_hb[b * Hh + i];
    }
    __syncthreads();
    float s = 0.f;
    for (int i = tid; i < 1024; i += 256) s += v[i];
    red[tid] = s; __syncthreads();
    for (int st = 128; st > 0; st >>= 1) { if (tid < st) red[tid] += red[tid + st]; __syncthreads(); }
    float mu = red[0] * (1.0f / 1024.0f);
    __syncthreads();
    s = 0.f;
    for (int i = tid; i < 1024; i += 256) { float dd = v[i] - mu; s += dd * dd; }
    red[tid] = s; __syncthreads();
    for (int st = 128; st > 0; st >>= 1) { if (tid < st) red[tid] += red[tid + st]; __syncthreads(); }
    float rstd = rsqrtf(red[0] * (1.0f / 1024.0f) + 1e-5f);
    __syncthreads();
    for (int i = tid; i < 1024; i += 256) v[i] = (v[i] - mu) * rstd * ln_g[i] + ln_b[i];
    __syncthreads();
    float part = 0.f;
    for (int jj = tid; jj < Hh; jj += 256) {
        float acc = b1[jj];
        const float* wr = w1 + (size_t)jj * 1024;
#pragma unroll 4
        for (int k2 = 0; k2 < 1024; k2++) acc += v[k2] * wr[k2];
        part += fmaxf(acc, 0.f) * w2[jj];
    }
    red[tid] = part; __syncthreads();
    for (int st = 128; st > 0; st >>= 1) { if (tid < st) red[tid] += red[tid + st]; __syncthreads(); }
    if (tid == 0) out[b] = red[0] + b2[0];
}

// ---------------- launch ----------------
extern "C" void kernel_launch(void* const* d_in, const int* in_sizes, int n_in,
                              void* d_out, int out_size)
{
    (void)in_sizes; (void)n_in; (void)out_size;
    const float* x     = (const float*)d_in[0];
    const float* w_ih0 = (const float*)d_in[1];
    const float* w_hh0 = (const float*)d_in[2];
    const float* b_ih0 = (const float*)d_in[3];
    const float* b_hh0 = (const float*)d_in[4];
    const float* w_ih1 = (const float*)d_in[5];
    const float* w_hh1 = (const float*)d_in[6];
    const float* b_ih1 = (const float*)d_in[7];
    const float* b_hh1 = (const float*)d_in[8];
    const float* ln_g  = (const float*)d_in[9];
    const float* ln_b  = (const float*)d_in[10];
    const float* w1    = (const float*)d_in[11];
    const float* b1    = (const float*)d_in[12];
    const float* w2    = (const float*)d_in[13];
    const float* b2    = (const float*)d_in[14];
    float* out = (float*)d_out;

    cudaFuncSetAttribute(k_mma_gemm, cudaFuncAttributeMaxDynamicSharedMemorySize, MMSM);

    void *p_gx1b, *p_o0last, *p_w1h, *p_w1l;
    cudaGetSymbolAddress(&p_gx1b, g_gx1b);
    cudaGetSymbolAddress(&p_o0last, g_o0last);
    cudaGetSymbolAddress(&p_w1h, g_w1h);
    cudaGetSymbolAddress(&p_w1l, g_w1l);

    k_prepx<<<16384, 256>>>(x);                                          // 0
    k_prepw<<<6656, 256>>>(w_ih0, w_hh0);                                // 1
    k_prep1<<<14336, 256>>>(w_ih1, w_hh1);                               // 2

    // layer 0 bidirectional fused scan  <- profiled (slot 5 = 2 harness + 3)
    k_scan_mma<true><<<dim3(64, 2), 256>>>(b_ih0, b_hh0);                // 3

    // layer 1 bwd projection (only t = T-1): gx1b = o0[T-1] @ w_ih1[dir1]^T + b
    k_mma_gemm<<<dim3(16, 1), 256, MMSM>>>(                              // 4
        (const __half*)p_o0last, (const __half*)p_w1h, (const __half*)p_w1l,
        b_ih1 + G, b_hh1 + G, (float*)p_gx1b, Bsz, 2 * Hh);

    // layer 1 forward fused scan
    k_scan_mma<false><<<64, 256>>>(b_ih1, b_hh1);                        // 5

    k_l1bwd<<<128, 256>>>();                                             // 6
    k_head<<<64, 256>>>(ln_g, ln_b, w1, b1, w2, b2, out);                // 7
}